// round 10
// baseline (speedup 1.0000x reference)
#include <cuda_runtime.h>
#include <cuda_fp16.h>
#include <cstdint>

// MOELinearB: out[e] = x[e] @ W[e]^T, E=8, N=4096, R=128, OUT=4096, fp32.
// R10: MIO-relief build.
//   - A fragments held in regs full-K (no per-tile A LDSM), warp tile 32x32.
//   - Epilogue: STS to smem staging + per-row 1D cp.async.bulk (UBLKCP) to
//     global -> STG issue cost leaves the LSU pipe.
//   - CTA 128x64 tile, 8-tile N-stripe, B cp.async double-buffered, 2 CTAs/SM.

#define E_   8
#define N_   4096
#define R_   128
#define OUT_ 4096

#define BM 128
#define BN 64
#define NTILE 8
#define THREADS 256

#define XTOT (E_ * N_ * R_)
#define WTOT (E_ * OUT_ * R_)

__device__ __half g_xh[XTOT];
__device__ __half g_wh[WTOT];

// Row stride 272 B: (17r + c) mod 8 permutation -> cp.async/ldmatrix/STS all
// bank-conflict-free; 272 = 17*16 keeps 16B alignment for bulk copies.
#define RSTRIDE_B 272
#define A_REGION   (128 * RSTRIDE_B)          // 34816
#define B_REGION   (64 * RSTRIDE_B)           // 17408
#define OUT_REGION (128 * RSTRIDE_B)          // 34816 (128 rows x 256B data)
#define OFF_A   0
#define OFF_B0  (A_REGION)
#define OFF_B1  (A_REGION + B_REGION)
#define OFF_OUT (A_REGION + 2 * B_REGION)
#define SMEM_BYTES (OFF_OUT + OUT_REGION)     // 104448 -> 2 CTAs/SM

// ---------------- Kernel 1: fp32 -> fp16 ----------------
__global__ __launch_bounds__(256)
void convert_kernel(const float* __restrict__ X, const float* __restrict__ Wt)
{
    const int idx = blockIdx.x * blockDim.x + threadIdx.x;
    const int xq = XTOT / 4;
    const float4* src;
    uint2* dst;
    int base;
    if (idx < xq) {
        src = reinterpret_cast<const float4*>(X);
        dst = reinterpret_cast<uint2*>(g_xh);
        base = idx;
    } else {
        src = reinterpret_cast<const float4*>(Wt);
        dst = reinterpret_cast<uint2*>(g_wh);
        base = idx - xq;
    }
    float4 v = src[base];
    __half2 p0 = __floats2half2_rn(v.x, v.y);
    __half2 p1 = __floats2half2_rn(v.z, v.w);
    dst[base] = make_uint2(*reinterpret_cast<uint32_t*>(&p0),
                           *reinterpret_cast<uint32_t*>(&p1));
}

// ---------------- Kernel 2: GEMM ----------------
static __device__ __forceinline__ void mma_f16(float* d, const uint32_t* a,
                                               const uint32_t* b) {
    asm volatile(
        "mma.sync.aligned.m16n8k16.row.col.f32.f16.f16.f32 "
        "{%0,%1,%2,%3}, {%4,%5,%6,%7}, {%8,%9}, {%0,%1,%2,%3};"
        : "+f"(d[0]), "+f"(d[1]), "+f"(d[2]), "+f"(d[3])
        : "r"(a[0]), "r"(a[1]), "r"(a[2]), "r"(a[3]), "r"(b[0]), "r"(b[1]));
}

static __device__ __forceinline__ void ldsm4(uint32_t* r, uint32_t addr) {
    asm volatile("ldmatrix.sync.aligned.m8n8.x4.shared.b16 {%0,%1,%2,%3}, [%4];"
                 : "=r"(r[0]), "=r"(r[1]), "=r"(r[2]), "=r"(r[3]) : "r"(addr));
}

static __device__ __forceinline__ void cp16(uint32_t dst, const void* src) {
    asm volatile("cp.async.cg.shared.global [%0], [%1], 16;"
                 :: "r"(dst), "l"(src) : "memory");
}

static __device__ __forceinline__ uint32_t smem_u32(const void* p) {
    uint32_t a;
    asm("{ .reg .u64 t; cvta.to.shared.u64 t, %1; cvt.u32.u64 %0, t; }"
        : "=r"(a) : "l"(p));
    return a;
}

__global__ __launch_bounds__(THREADS, 2)
void moe_f16_mma_kernel(float* __restrict__ O)
{
    extern __shared__ char smem[];
    const uint32_t sbase = smem_u32(smem);
    const uint32_t sA   = sbase + OFF_A;
    const uint32_t sB0  = sbase + OFF_B0;
    const uint32_t sB1  = sbase + OFF_B1;
    const uint32_t sOut = sbase + OFF_OUT;

    const int tid  = threadIdx.x;
    const int wid  = tid >> 5;
    const int lane = tid & 31;
    const int grp  = lane >> 2;
    const int qc   = lane & 3;
    const int wm   = wid >> 1;   // 0..3 -> M offset wm*32
    const int wn   = wid & 1;    // 0..1 -> N offset wn*32

    const int e   = blockIdx.z;
    const int bm  = blockIdx.y * BM;
    const int bn0 = blockIdx.x * (BN * NTILE);   // 512-wide stripe

    const __half* A  = g_xh + (size_t)e * N_   * R_ + (size_t)bm * R_;
    const __half* Bg = g_wh + (size_t)e * OUT_ * R_ + (size_t)bn0 * R_;
    float* C = O + (size_t)e * N_ * OUT_;

    // ldmatrix per-lane offsets
    const uint32_t a_loff = (uint32_t)((wm * 32 + (lane & 15)) * RSTRIDE_B
                                       + (lane >> 4) * 16);
    const uint32_t b_loff = (uint32_t)((wn * 32 + ((lane >> 4) & 1) * 8 + (lane & 7)) * RSTRIDE_B
                                       + ((lane >> 3) & 1) * 16);

    // ---- prologue: stage A + B0 (group 0), B1 (group 1) ----
#pragma unroll
    for (int it = 0; it < 8; it++) {          // A: 2048 16B-chunks
        const int idx = tid + it * THREADS;
        const int row = idx >> 4;
        const int c   = idx & 15;
        cp16(sA + (uint32_t)(row * RSTRIDE_B + c * 16), A + row * R_ + c * 8);
    }
#pragma unroll
    for (int it = 0; it < 4; it++) {          // B0: 1024 chunks
        const int idx = tid + it * THREADS;
        const int row = idx >> 4;
        const int c   = idx & 15;
        cp16(sB0 + (uint32_t)(row * RSTRIDE_B + c * 16), Bg + row * R_ + c * 8);
    }
    asm volatile("cp.async.commit_group;" ::: "memory");
#pragma unroll
    for (int it = 0; it < 4; it++) {          // B1
        const int idx = tid + it * THREADS;
        const int row = idx >> 4;
        const int c   = idx & 15;
        cp16(sB1 + (uint32_t)(row * RSTRIDE_B + c * 16),
             Bg + (size_t)BN * R_ + row * R_ + c * 8);
    }
    asm volatile("cp.async.commit_group;" ::: "memory");

    // A + B0 ready; pull ALL A fragments into registers (full K, 64 regs).
    asm volatile("cp.async.wait_group 1;" ::: "memory");
    __syncthreads();

    uint32_t ah[8][8];   // [ks][mt*4+i], warp rows wm*32..wm*32+31
#pragma unroll
    for (int ks = 0; ks < 8; ks++)
#pragma unroll
        for (int mt = 0; mt < 2; mt++)
            ldsm4(ah[ks] + mt * 4,
                  sA + a_loff + (uint32_t)(mt * 16 * RSTRIDE_B) + (uint32_t)(ks * 32));

#pragma unroll 1
    for (int t = 0; t < NTILE; t++) {
        if (t > 0) {
            asm volatile("cp.async.wait_group 0;" ::: "memory");
            __syncthreads();   // B(t) visible; everyone past buf((t+1)&1)
            if (t + 1 < NTILE) {
                const uint32_t sb = (((t + 1) & 1) ? sB1 : sB0);
                const __half* Bt = Bg + (size_t)(t + 1) * BN * R_;
#pragma unroll
                for (int it = 0; it < 4; it++) {
                    const int idx = tid + it * THREADS;
                    const int row = idx >> 4;
                    const int c   = idx & 15;
                    cp16(sb + (uint32_t)(row * RSTRIDE_B + c * 16),
                         Bt + row * R_ + c * 8);
                }
                asm volatile("cp.async.commit_group;" ::: "memory");
            }
        }

        const uint32_t bR = ((t & 1) ? sB1 : sB0);

        float acc[2][4][4];
#pragma unroll
        for (int mt = 0; mt < 2; mt++)
#pragma unroll
            for (int nt = 0; nt < 4; nt++)
#pragma unroll
                for (int q = 0; q < 4; q++)
                    acc[mt][nt][q] = 0.0f;

#pragma unroll
        for (int ks = 0; ks < 8; ks++) {
            const uint32_t kso = (uint32_t)(ks * 32);
            uint32_t bh[8];
            ldsm4(bh + 0, bR + b_loff + 0 * 16 * RSTRIDE_B + kso);  // nt 0,1
            ldsm4(bh + 4, bR + b_loff + 1 * 16 * RSTRIDE_B + kso);  // nt 2,3
#pragma unroll
            for (int mt = 0; mt < 2; mt++)
#pragma unroll
                for (int nt = 0; nt < 4; nt++)
                    mma_f16(acc[mt][nt], ah[ks] + mt * 4, bh + nt * 2);
        }

        // ---- epilogue tile t: STS -> smem stage, then per-row bulk copies ----
        // 1) make sure the bulk engine finished READING the stage (tile t-1)
        if (tid < 128) {
            asm volatile("cp.async.bulk.wait_group.read 0;" ::: "memory");
        }
        __syncthreads();
        // 2) all threads store their fragments (row stride 272 B, conflict-free)
#pragma unroll
        for (int mt = 0; mt < 2; mt++) {
#pragma unroll
            for (int nt = 0; nt < 4; nt++) {
                const int r0  = wm * 32 + mt * 16 + grp;
                const int col = wn * 32 + nt * 8 + qc * 2;
                float2 v0 = make_float2(acc[mt][nt][0], acc[mt][nt][1]);
                float2 v1 = make_float2(acc[mt][nt][2], acc[mt][nt][3]);
                *reinterpret_cast<float2*>(smem + OFF_OUT + r0 * RSTRIDE_B + col * 4) = v0;
                *reinterpret_cast<float2*>(smem + OFF_OUT + (r0 + 8) * RSTRIDE_B + col * 4) = v1;
            }
        }
        __syncthreads();
        // 3) 128 threads each push one 256B row shared->global via bulk engine
        if (tid < 128) {
            asm volatile("fence.proxy.async.shared::cta;" ::: "memory");
            const float* gdst = C + (size_t)(bm + tid) * OUT_ + (bn0 + t * BN);
            asm volatile("cp.async.bulk.global.shared::cta.bulk_group [%0], [%1], %2;"
                         :: "l"(gdst), "r"(sOut + (uint32_t)(tid * RSTRIDE_B)),
                            "r"(BN * 4) : "memory");
            asm volatile("cp.async.bulk.commit_group;" ::: "memory");
        }
    }
}

extern "C" void kernel_launch(void* const* d_in, const int* in_sizes, int n_in,
                              void* d_out, int out_size)
{
    const float* x = (const float*)d_in[0];   // [E, N, R]
    const float* w = (const float*)d_in[1];   // [E, OUT, R]
    float* out = (float*)d_out;               // [E, N, OUT]

    const int nvec = (XTOT + WTOT) / 4;
    convert_kernel<<<nvec / 256, 256>>>(x, w);

    cudaFuncSetAttribute(moe_f16_mma_kernel,
                         cudaFuncAttributeMaxDynamicSharedMemorySize, SMEM_BYTES);
    dim3 grid(OUT_ / (BN * NTILE), N_ / BM, E_);   // (8, 32, 8) = 2048 CTAs
    moe_f16_mma_kernel<<<grid, THREADS, SMEM_BYTES>>>(out);
}

// round 11
// speedup vs baseline: 1.1311x; 1.1311x over previous
#include <cuda_runtime.h>
#include <cuda_fp16.h>
#include <cstdint>

// MOELinearB: out[e] = x[e] @ W[e]^T, E=8, N=4096, R=128, OUT=4096, fp32.
// R11: deep B pipeline. A fragments in regs (full K), 128x64 tiles over an
// 8-tile N-stripe, FOUR B smem buffers (3 tiles of prefetch lead), one
// __syncthreads per tile, streaming STG.64 epilogue. 2 CTAs/SM.

#define E_   8
#define N_   4096
#define R_   128
#define OUT_ 4096

#define BM 128
#define BN 64
#define NTILE 8
#define THREADS 256

#define XTOT (E_ * N_ * R_)
#define WTOT (E_ * OUT_ * R_)

__device__ __half g_xh[XTOT];
__device__ __half g_wh[WTOT];

// Row stride 272 B: (17r + c) mod 8 permutation -> cp.async stores and
// ldmatrix reads bank-conflict-free.
#define RSTRIDE_B 272
#define A_REGION  (128 * RSTRIDE_B)            // 34816
#define B_REGION  (64 * RSTRIDE_B)             // 17408
#define NBUF 4
#define SMEM_BYTES (A_REGION + NBUF * B_REGION) // 104448 -> 2 CTAs/SM

// ---------------- Kernel 1: fp32 -> fp16 ----------------
__global__ __launch_bounds__(256)
void convert_kernel(const float* __restrict__ X, const float* __restrict__ Wt)
{
    const int idx = blockIdx.x * blockDim.x + threadIdx.x;
    const int xq = XTOT / 4;
    const float4* src;
    uint2* dst;
    int base;
    if (idx < xq) {
        src = reinterpret_cast<const float4*>(X);
        dst = reinterpret_cast<uint2*>(g_xh);
        base = idx;
    } else {
        src = reinterpret_cast<const float4*>(Wt);
        dst = reinterpret_cast<uint2*>(g_wh);
        base = idx - xq;
    }
    float4 v = src[base];
    __half2 p0 = __floats2half2_rn(v.x, v.y);
    __half2 p1 = __floats2half2_rn(v.z, v.w);
    dst[base] = make_uint2(*reinterpret_cast<uint32_t*>(&p0),
                           *reinterpret_cast<uint32_t*>(&p1));
}

// ---------------- Kernel 2: GEMM ----------------
static __device__ __forceinline__ void mma_f16(float* d, const uint32_t* a,
                                               const uint32_t* b) {
    asm volatile(
        "mma.sync.aligned.m16n8k16.row.col.f32.f16.f16.f32 "
        "{%0,%1,%2,%3}, {%4,%5,%6,%7}, {%8,%9}, {%0,%1,%2,%3};"
        : "+f"(d[0]), "+f"(d[1]), "+f"(d[2]), "+f"(d[3])
        : "r"(a[0]), "r"(a[1]), "r"(a[2]), "r"(a[3]), "r"(b[0]), "r"(b[1]));
}

static __device__ __forceinline__ void ldsm4(uint32_t* r, uint32_t addr) {
    asm volatile("ldmatrix.sync.aligned.m8n8.x4.shared.b16 {%0,%1,%2,%3}, [%4];"
                 : "=r"(r[0]), "=r"(r[1]), "=r"(r[2]), "=r"(r[3]) : "r"(addr));
}

static __device__ __forceinline__ void cp16(uint32_t dst, const void* src) {
    asm volatile("cp.async.cg.shared.global [%0], [%1], 16;"
                 :: "r"(dst), "l"(src) : "memory");
}

static __device__ __forceinline__ uint32_t smem_u32(const void* p) {
    uint32_t a;
    asm("{ .reg .u64 t; cvta.to.shared.u64 t, %1; cvt.u32.u64 %0, t; }"
        : "=r"(a) : "l"(p));
    return a;
}

__global__ __launch_bounds__(THREADS, 2)
void moe_f16_mma_kernel(float* __restrict__ O)
{
    extern __shared__ char smem[];
    const uint32_t sbase = smem_u32(smem);
    const uint32_t sA = sbase;

    const int tid  = threadIdx.x;
    const int wid  = tid >> 5;
    const int lane = tid & 31;
    const int grp  = lane >> 2;
    const int qc   = lane & 3;
    const int wm   = wid >> 1;   // 0..3 -> M offset wm*32
    const int wn   = wid & 1;    // 0..1 -> N offset wn*32

    const int e   = blockIdx.z;
    const int bm  = blockIdx.y * BM;
    const int bn0 = blockIdx.x * (BN * NTILE);   // 512-wide stripe

    const __half* A  = g_xh + (size_t)e * N_   * R_ + (size_t)bm * R_;
    const __half* Bg = g_wh + (size_t)e * OUT_ * R_ + (size_t)bn0 * R_;
    float* C = O + (size_t)e * N_ * OUT_;

    // ldmatrix per-lane offsets
    const uint32_t a_loff = (uint32_t)((wm * 32 + (lane & 15)) * RSTRIDE_B
                                       + (lane >> 4) * 16);
    const uint32_t b_loff = (uint32_t)((wn * 32 + ((lane >> 4) & 1) * 8 + (lane & 7)) * RSTRIDE_B
                                       + ((lane >> 3) & 1) * 16);

    // B staging helper: 64 rows x 16 chunks = 1024 chunks, 4 per thread.
    const int s_row = tid >> 4;          // 0..15 (+16 per it)
    const int s_c   = tid & 15;

    // ---- prologue: G0 = {A, B0}, G1 = {B1}, G2 = {B2} ----
#pragma unroll
    for (int it = 0; it < 8; it++) {     // A: 2048 chunks
        const int idx = tid + it * THREADS;
        const int row = idx >> 4;
        const int c   = idx & 15;
        cp16(sA + (uint32_t)(row * RSTRIDE_B + c * 16), A + row * R_ + c * 8);
    }
#pragma unroll
    for (int it = 0; it < 4; it++) {
        const int row = s_row + it * 16;
        cp16(sbase + A_REGION + (uint32_t)(row * RSTRIDE_B + s_c * 16),
             Bg + row * R_ + s_c * 8);
    }
    asm volatile("cp.async.commit_group;" ::: "memory");
#pragma unroll
    for (int b = 1; b <= 2; b++) {
#pragma unroll
        for (int it = 0; it < 4; it++) {
            const int row = s_row + it * 16;
            cp16(sbase + A_REGION + (uint32_t)(b * B_REGION)
                     + (uint32_t)(row * RSTRIDE_B + s_c * 16),
                 Bg + (size_t)b * BN * R_ + row * R_ + s_c * 8);
        }
        asm volatile("cp.async.commit_group;" ::: "memory");
    }

    // A + B0 complete (leave B1, B2 in flight); pull A fragments into regs.
    asm volatile("cp.async.wait_group 2;" ::: "memory");
    __syncthreads();

    uint32_t ah[8][8];   // [ks][mt*4+i]
#pragma unroll
    for (int ks = 0; ks < 8; ks++)
#pragma unroll
        for (int mt = 0; mt < 2; mt++)
            ldsm4(ah[ks] + mt * 4,
                  sA + a_loff + (uint32_t)(mt * 16 * RSTRIDE_B) + (uint32_t)(ks * 32));

#pragma unroll 1
    for (int t = 0; t < NTILE; t++) {
        if (t > 0) {
            // allow at most min(2, NTILE-1-t) groups in flight => B(t) done
            const int pend = (NTILE - 1 - t) < 2 ? (NTILE - 1 - t) : 2;
            switch (pend) {
                case 2:  asm volatile("cp.async.wait_group 2;" ::: "memory"); break;
                case 1:  asm volatile("cp.async.wait_group 1;" ::: "memory"); break;
                default: asm volatile("cp.async.wait_group 0;" ::: "memory"); break;
            }
            __syncthreads();   // B(t) visible; all warps past buf((t+3)&3)
        }

        // stage B(t+3) into buf (t+3)&3 (read last in tile t-1; safe now)
        if (t + 3 < NTILE) {
            const uint32_t sb = sbase + A_REGION
                              + (uint32_t)(((t + 3) & 3) * B_REGION);
            const __half* Bt = Bg + (size_t)(t + 3) * BN * R_;
#pragma unroll
            for (int it = 0; it < 4; it++) {
                const int row = s_row + it * 16;
                cp16(sb + (uint32_t)(row * RSTRIDE_B + s_c * 16),
                     Bt + row * R_ + s_c * 8);
            }
            asm volatile("cp.async.commit_group;" ::: "memory");
        }

        const uint32_t bR = sbase + A_REGION + (uint32_t)((t & 3) * B_REGION);

        float acc[2][4][4];
#pragma unroll
        for (int mt = 0; mt < 2; mt++)
#pragma unroll
            for (int nt = 0; nt < 4; nt++)
#pragma unroll
                for (int q = 0; q < 4; q++)
                    acc[mt][nt][q] = 0.0f;

#pragma unroll
        for (int ks = 0; ks < 8; ks++) {
            const uint32_t kso = (uint32_t)(ks * 32);
            uint32_t bh[8];
            ldsm4(bh + 0, bR + b_loff + 0 * 16 * RSTRIDE_B + kso);  // nt 0,1
            ldsm4(bh + 4, bR + b_loff + 1 * 16 * RSTRIDE_B + kso);  // nt 2,3
#pragma unroll
            for (int mt = 0; mt < 2; mt++)
#pragma unroll
                for (int nt = 0; nt < 4; nt++)
                    mma_f16(acc[mt][nt], ah[ks] + mt * 4, bh + nt * 2);
        }

        // ---- epilogue tile t: streaming stores drain under later tiles ----
        const int colb = bn0 + t * BN;
#pragma unroll
        for (int mt = 0; mt < 2; mt++) {
#pragma unroll
            for (int nt = 0; nt < 4; nt++) {
                const int row = bm + wm * 32 + mt * 16 + grp;
                const int col = colb + wn * 32 + nt * 8 + qc * 2;
                float2 v0 = make_float2(acc[mt][nt][0], acc[mt][nt][1]);
                float2 v1 = make_float2(acc[mt][nt][2], acc[mt][nt][3]);
                __stcs(reinterpret_cast<float2*>(C + (size_t)row * OUT_ + col), v0);
                __stcs(reinterpret_cast<float2*>(C + (size_t)(row + 8) * OUT_ + col), v1);
            }
        }
    }
}

extern "C" void kernel_launch(void* const* d_in, const int* in_sizes, int n_in,
                              void* d_out, int out_size)
{
    const float* x = (const float*)d_in[0];   // [E, N, R]
    const float* w = (const float*)d_in[1];   // [E, OUT, R]
    float* out = (float*)d_out;               // [E, N, OUT]

    const int nvec = (XTOT + WTOT) / 4;
    convert_kernel<<<nvec / 256, 256>>>(x, w);

    cudaFuncSetAttribute(moe_f16_mma_kernel,
                         cudaFuncAttributeMaxDynamicSharedMemorySize, SMEM_BYTES);
    dim3 grid(OUT_ / (BN * NTILE), N_ / BM, E_);   // (8, 32, 8) = 2048 CTAs
    moe_f16_mma_kernel<<<grid, THREADS, SMEM_BYTES>>>(out);
}

// round 12
// speedup vs baseline: 1.1941x; 1.0557x over previous
#include <cuda_runtime.h>
#include <cuda_fp16.h>
#include <cstdint>

// MOELinearB: out[e] = x[e] @ W[e]^T, E=8, N=4096, R=128, OUT=4096, fp32.
// R12: persistent-CTA work-stealing GEMM. 296 CTAs (2/SM) pop 128x512 stripe
// jobs from an atomic queue. Per job: A fragments in regs (full K), 8 B-tiles
// through 4 smem buffers, one barrier + wait_group 2 per tile. Next job's
// A/B0/B1/B2 staged during tiles 5-7 of the current job -> continuous store
// stream, no wave transitions.

#define E_   8
#define N_   4096
#define R_   128
#define OUT_ 4096

#define BM 128
#define BN 64
#define NTILE 8
#define THREADS 256
#define NCTA 296
#define NJOBS (E_ * (N_ / BM) * (OUT_ / (BN * NTILE)))   // 8*32*8 = 2048

#define XTOT (E_ * N_ * R_)
#define WTOT (E_ * OUT_ * R_)

__device__ __half g_xh[XTOT];
__device__ __half g_wh[WTOT];
__device__ int    g_job_ctr;

// Row stride 272 B: (17r + c) mod 8 permutation -> cp.async stores and
// ldmatrix reads bank-conflict-free.
#define RSTRIDE_B 272
#define A_REGION  (128 * RSTRIDE_B)             // 34816
#define B_REGION  (64 * RSTRIDE_B)              // 17408
#define OFF_CTRL  (A_REGION + 4 * B_REGION)     // 104448
#define SMEM_BYTES (OFF_CTRL + 16)              // 104464 -> 2 CTAs/SM

// ---------------- Kernel 1: fp32 -> fp16 (+ job counter reset) ----------------
__global__ __launch_bounds__(256)
void convert_kernel(const float* __restrict__ X, const float* __restrict__ Wt)
{
    if (blockIdx.x == 0 && threadIdx.x == 0) g_job_ctr = NCTA;

    const int idx = blockIdx.x * blockDim.x + threadIdx.x;
    const int xq = XTOT / 4;
    const float4* src;
    uint2* dst;
    int base;
    if (idx < xq) {
        src = reinterpret_cast<const float4*>(X);
        dst = reinterpret_cast<uint2*>(g_xh);
        base = idx;
    } else {
        src = reinterpret_cast<const float4*>(Wt);
        dst = reinterpret_cast<uint2*>(g_wh);
        base = idx - xq;
    }
    float4 v = src[base];
    __half2 p0 = __floats2half2_rn(v.x, v.y);
    __half2 p1 = __floats2half2_rn(v.z, v.w);
    dst[base] = make_uint2(*reinterpret_cast<uint32_t*>(&p0),
                           *reinterpret_cast<uint32_t*>(&p1));
}

// ---------------- Kernel 2: GEMM ----------------
static __device__ __forceinline__ void mma_f16(float* d, const uint32_t* a,
                                               const uint32_t* b) {
    asm volatile(
        "mma.sync.aligned.m16n8k16.row.col.f32.f16.f16.f32 "
        "{%0,%1,%2,%3}, {%4,%5,%6,%7}, {%8,%9}, {%0,%1,%2,%3};"
        : "+f"(d[0]), "+f"(d[1]), "+f"(d[2]), "+f"(d[3])
        : "r"(a[0]), "r"(a[1]), "r"(a[2]), "r"(a[3]), "r"(b[0]), "r"(b[1]));
}

static __device__ __forceinline__ void ldsm4(uint32_t* r, uint32_t addr) {
    asm volatile("ldmatrix.sync.aligned.m8n8.x4.shared.b16 {%0,%1,%2,%3}, [%4];"
                 : "=r"(r[0]), "=r"(r[1]), "=r"(r[2]), "=r"(r[3]) : "r"(addr));
}

static __device__ __forceinline__ void cp16(uint32_t dst, const void* src) {
    asm volatile("cp.async.cg.shared.global [%0], [%1], 16;"
                 :: "r"(dst), "l"(src) : "memory");
}

static __device__ __forceinline__ uint32_t smem_u32(const void* p) {
    uint32_t a;
    asm("{ .reg .u64 t; cvta.to.shared.u64 t, %1; cvt.u32.u64 %0, t; }"
        : "=r"(a) : "l"(p));
    return a;
}

static __device__ __forceinline__ void decode_job(int j, int& e, int& bm, int& bn0)
{
    e   = j >> 8;                 // 256 stripes per expert
    int rem = j & 255;
    bm  = (rem >> 3) << 7;        // 32 row-blocks
    bn0 = (rem & 7) << 9;         // 8 stripes of 512 cols
}

__global__ __launch_bounds__(THREADS, 2)
void moe_f16_mma_kernel(float* __restrict__ O)
{
    extern __shared__ char smem[];
    const uint32_t sbase = smem_u32(smem);
    const uint32_t sA = sbase;
    volatile int* ctrl = reinterpret_cast<volatile int*>(smem + OFF_CTRL);

    const int tid  = threadIdx.x;
    const int wid  = tid >> 5;
    const int lane = tid & 31;
    const int grp  = lane >> 2;
    const int qc   = lane & 3;
    const int wm   = wid >> 1;   // 0..3 -> M offset wm*32
    const int wn   = wid & 1;    // 0..1 -> N offset wn*32

    // staging maps
    const int s_row = tid >> 4;          // B: 0..15 (+16/iter)
    const int s_c   = tid & 15;

    // ldmatrix per-lane offsets
    const uint32_t a_loff = (uint32_t)((wm * 32 + (lane & 15)) * RSTRIDE_B
                                       + (lane >> 4) * 16);
    const uint32_t b_loff = (uint32_t)((wn * 32 + ((lane >> 4) & 1) * 8 + (lane & 7)) * RSTRIDE_B
                                       + ((lane >> 3) & 1) * 16);

    auto stageA = [&](const __half* Ap) {
#pragma unroll
        for (int it = 0; it < 8; it++) {
            const int idx = tid + it * THREADS;
            const int row = idx >> 4;
            const int c   = idx & 15;
            cp16(sA + (uint32_t)(row * RSTRIDE_B + c * 16), Ap + row * R_ + c * 8);
        }
    };
    auto stageB = [&](int bufi, const __half* Bp) {
        const uint32_t sb = sbase + A_REGION + (uint32_t)(bufi * B_REGION);
#pragma unroll
        for (int it = 0; it < 4; it++) {
            const int row = s_row + it * 16;
            cp16(sb + (uint32_t)(row * RSTRIDE_B + s_c * 16), Bp + row * R_ + s_c * 8);
        }
    };

    int job = blockIdx.x;

    // ---- prologue for first job: {A,B0} | {B1} | {B2} ----
    {
        int e, bm, bn0; decode_job(job, e, bm, bn0);
        const __half* A  = g_xh + (size_t)e * N_   * R_ + (size_t)bm * R_;
        const __half* Bg = g_wh + (size_t)e * OUT_ * R_ + (size_t)bn0 * R_;
        stageA(A);
        stageB(0, Bg);
        asm volatile("cp.async.commit_group;" ::: "memory");
        stageB(1, Bg + (size_t)BN * R_);
        asm volatile("cp.async.commit_group;" ::: "memory");
        stageB(2, Bg + (size_t)2 * BN * R_);
        asm volatile("cp.async.commit_group;" ::: "memory");
    }

    while (job < NJOBS) {
        int e, bm, bn0; decode_job(job, e, bm, bn0);
        const __half* Bg = g_wh + (size_t)e * OUT_ * R_ + (size_t)bn0 * R_;
        float* C = O + (size_t)e * N_ * OUT_;

        // job head: A + B0 of this job guaranteed complete
        asm volatile("cp.async.wait_group 2;" ::: "memory");
        __syncthreads();

        uint32_t ah[8][8];   // full-K A fragments in regs
#pragma unroll
        for (int ks = 0; ks < 8; ks++)
#pragma unroll
            for (int mt = 0; mt < 2; mt++)
                ldsm4(ah[ks] + mt * 4,
                      sA + a_loff + (uint32_t)(mt * 16 * RSTRIDE_B) + (uint32_t)(ks * 32));

        int nxt = NJOBS;

#pragma unroll 1
        for (int t = 0; t < NTILE; t++) {
            if (t > 0) {
                asm volatile("cp.async.wait_group 2;" ::: "memory");
                __syncthreads();
            }

            // head-of-tile staging (exactly one commit group per tile)
            if (t < 5) {
                stageB((t + 3) & 3, Bg + (size_t)(t + 3) * BN * R_);
                asm volatile("cp.async.commit_group;" ::: "memory");
            } else if (t == 5) {
                nxt = ctrl[0];
                if (nxt < NJOBS) {
                    int e2, bm2, bn2; decode_job(nxt, e2, bm2, bn2);
                    stageA(g_xh + (size_t)e2 * N_ * R_ + (size_t)bm2 * R_);
                    stageB(0, g_wh + (size_t)e2 * OUT_ * R_ + (size_t)bn2 * R_);
                    asm volatile("cp.async.commit_group;" ::: "memory");
                }
            } else if (t == 6) {
                if (nxt < NJOBS) {
                    int e2, bm2, bn2; decode_job(nxt, e2, bm2, bn2);
                    stageB(1, g_wh + (size_t)e2 * OUT_ * R_ + (size_t)bn2 * R_
                              + (size_t)BN * R_);
                    asm volatile("cp.async.commit_group;" ::: "memory");
                }
            } else {  // t == 7
                if (nxt < NJOBS) {
                    int e2, bm2, bn2; decode_job(nxt, e2, bm2, bn2);
                    stageB(2, g_wh + (size_t)e2 * OUT_ * R_ + (size_t)bn2 * R_
                              + (size_t)2 * BN * R_);
                    asm volatile("cp.async.commit_group;" ::: "memory");
                }
            }
            if (t == 4 && tid == 0) ctrl[0] = atomicAdd(&g_job_ctr, 1);

            const uint32_t bR = sbase + A_REGION + (uint32_t)((t & 3) * B_REGION);

            float acc[2][4][4];
#pragma unroll
            for (int mt = 0; mt < 2; mt++)
#pragma unroll
                for (int nt = 0; nt < 4; nt++)
#pragma unroll
                    for (int q = 0; q < 4; q++)
                        acc[mt][nt][q] = 0.0f;

#pragma unroll
            for (int ks = 0; ks < 8; ks++) {
                const uint32_t kso = (uint32_t)(ks * 32);
                uint32_t bh[8];
                ldsm4(bh + 0, bR + b_loff + 0 * 16 * RSTRIDE_B + kso);
                ldsm4(bh + 4, bR + b_loff + 1 * 16 * RSTRIDE_B + kso);
#pragma unroll
                for (int mt = 0; mt < 2; mt++)
#pragma unroll
                    for (int nt = 0; nt < 4; nt++)
                        mma_f16(acc[mt][nt], ah[ks] + mt * 4, bh + nt * 2);
            }

            // epilogue tile t: streaming stores
            const int colb = bn0 + t * BN;
#pragma unroll
            for (int mt = 0; mt < 2; mt++) {
#pragma unroll
                for (int nt = 0; nt < 4; nt++) {
                    const int row = bm + wm * 32 + mt * 16 + grp;
                    const int col = colb + wn * 32 + nt * 8 + qc * 2;
                    float2 v0 = make_float2(acc[mt][nt][0], acc[mt][nt][1]);
                    float2 v1 = make_float2(acc[mt][nt][2], acc[mt][nt][3]);
                    __stcs(reinterpret_cast<float2*>(C + (size_t)row * OUT_ + col), v0);
                    __stcs(reinterpret_cast<float2*>(C + (size_t)(row + 8) * OUT_ + col), v1);
                }
            }
        }

        job = nxt;
    }
}

extern "C" void kernel_launch(void* const* d_in, const int* in_sizes, int n_in,
                              void* d_out, int out_size)
{
    const float* x = (const float*)d_in[0];   // [E, N, R]
    const float* w = (const float*)d_in[1];   // [E, OUT, R]
    float* out = (float*)d_out;               // [E, N, OUT]

    const int nvec = (XTOT + WTOT) / 4;
    convert_kernel<<<nvec / 256, 256>>>(x, w);

    cudaFuncSetAttribute(moe_f16_mma_kernel,
                         cudaFuncAttributeMaxDynamicSharedMemorySize, SMEM_BYTES);
    moe_f16_mma_kernel<<<NCTA, THREADS, SMEM_BYTES>>>(out);
}

// round 13
// speedup vs baseline: 1.3253x; 1.1098x over previous
#include <cuda_runtime.h>
#include <cuda_fp16.h>
#include <cstdint>

// MOELinearB: out[e] = x[e] @ W[e]^T, E=8, N=4096, R=128, OUT=4096, fp32.
// R13: R12 persistent work-stealing GEMM + permuted-B STG.128 epilogue.
//   B columns are permuted in smem (pi) so each thread's values from an
//   nt-pair form 4 consecutive output columns -> 8x STG.128 per thread
//   instead of 16x STG.64 (23% fewer store-issue cycles, same bytes).

#define E_   8
#define N_   4096
#define R_   128
#define OUT_ 4096

#define BM 128
#define BN 64
#define NTILE 8
#define THREADS 256
#define NCTA 296
#define NJOBS (E_ * (N_ / BM) * (OUT_ / (BN * NTILE)))   // 2048

#define XTOT (E_ * N_ * R_)
#define WTOT (E_ * OUT_ * R_)

__device__ __half g_xh[XTOT];
__device__ __half g_wh[WTOT];
__device__ int    g_job_ctr;

#define RSTRIDE_B 272
#define A_REGION  (128 * RSTRIDE_B)             // 34816
#define B_REGION  (64 * RSTRIDE_B)              // 17408
#define OFF_CTRL  (A_REGION + 4 * B_REGION)     // 104448
#define SMEM_BYTES (OFF_CTRL + 16)              // 104464 -> 2 CTAs/SM

// ---------------- Kernel 1: fp32 -> fp16 (+ job counter reset) ----------------
__global__ __launch_bounds__(256)
void convert_kernel(const float* __restrict__ X, const float* __restrict__ Wt)
{
    if (blockIdx.x == 0 && threadIdx.x == 0) g_job_ctr = NCTA;

    const int idx = blockIdx.x * blockDim.x + threadIdx.x;
    const int xq = XTOT / 4;
    const float4* src;
    uint2* dst;
    int base;
    if (idx < xq) {
        src = reinterpret_cast<const float4*>(X);
        dst = reinterpret_cast<uint2*>(g_xh);
        base = idx;
    } else {
        src = reinterpret_cast<const float4*>(Wt);
        dst = reinterpret_cast<uint2*>(g_wh);
        base = idx - xq;
    }
    float4 v = src[base];
    __half2 p0 = __floats2half2_rn(v.x, v.y);
    __half2 p1 = __floats2half2_rn(v.z, v.w);
    dst[base] = make_uint2(*reinterpret_cast<uint32_t*>(&p0),
                           *reinterpret_cast<uint32_t*>(&p1));
}

// ---------------- Kernel 2: GEMM ----------------
static __device__ __forceinline__ void mma_f16(float* d, const uint32_t* a,
                                               const uint32_t* b) {
    asm volatile(
        "mma.sync.aligned.m16n8k16.row.col.f32.f16.f16.f32 "
        "{%0,%1,%2,%3}, {%4,%5,%6,%7}, {%8,%9}, {%0,%1,%2,%3};"
        : "+f"(d[0]), "+f"(d[1]), "+f"(d[2]), "+f"(d[3])
        : "r"(a[0]), "r"(a[1]), "r"(a[2]), "r"(a[3]), "r"(b[0]), "r"(b[1]));
}

static __device__ __forceinline__ void ldsm4(uint32_t* r, uint32_t addr) {
    asm volatile("ldmatrix.sync.aligned.m8n8.x4.shared.b16 {%0,%1,%2,%3}, [%4];"
                 : "=r"(r[0]), "=r"(r[1]), "=r"(r[2]), "=r"(r[3]) : "r"(addr));
}

static __device__ __forceinline__ void cp16(uint32_t dst, const void* src) {
    asm volatile("cp.async.cg.shared.global [%0], [%1], 16;"
                 :: "r"(dst), "l"(src) : "memory");
}

static __device__ __forceinline__ uint32_t smem_u32(const void* p) {
    uint32_t a;
    asm("{ .reg .u64 t; cvta.to.shared.u64 t, %1; cvt.u32.u64 %0, t; }"
        : "=r"(a) : "l"(p));
    return a;
}

// B-column permutation: smem slot r holds W row pi(r) of the tile.
// r = nt*8 + j:  pi = (16-block) | (j>>1)<<2 | (nt&1)<<1 | (j&1)
// => fragment pair (nt=2p, 2p+1) at quad qc owns output cols p*16+qc*4+{0..3}.
static __device__ __forceinline__ int bperm(int r) {
    return (r & 48) | ((r & 6) << 1) | ((r >> 2) & 2) | (r & 1);
}

static __device__ __forceinline__ void decode_job(int j, int& e, int& bm, int& bn0)
{
    e   = j >> 8;
    int rem = j & 255;
    bm  = (rem >> 3) << 7;
    bn0 = (rem & 7) << 9;
}

__global__ __launch_bounds__(THREADS, 2)
void moe_f16_mma_kernel(float* __restrict__ O)
{
    extern __shared__ char smem[];
    const uint32_t sbase = smem_u32(smem);
    const uint32_t sA = sbase;
    volatile int* ctrl = reinterpret_cast<volatile int*>(smem + OFF_CTRL);

    const int tid  = threadIdx.x;
    const int wid  = tid >> 5;
    const int lane = tid & 31;
    const int grp  = lane >> 2;
    const int qc   = lane & 3;
    const int wm   = wid >> 1;   // 0..3 -> M offset wm*32
    const int wn   = wid & 1;    // 0..1 -> N offset wn*32

    const int s_row = tid >> 4;          // B staging: 0..15 (+16/iter)
    const int s_c   = tid & 15;

    const uint32_t a_loff = (uint32_t)((wm * 32 + (lane & 15)) * RSTRIDE_B
                                       + (lane >> 4) * 16);
    const uint32_t b_loff = (uint32_t)((wn * 32 + ((lane >> 4) & 1) * 8 + (lane & 7)) * RSTRIDE_B
                                       + ((lane >> 3) & 1) * 16);

    auto stageA = [&](const __half* Ap) {
#pragma unroll
        for (int it = 0; it < 8; it++) {
            const int idx = tid + it * THREADS;
            const int row = idx >> 4;
            const int c   = idx & 15;
            cp16(sA + (uint32_t)(row * RSTRIDE_B + c * 16), Ap + row * R_ + c * 8);
        }
    };
    // Stage B tile with permuted rows: slot row <- W row bperm(row & 63).
    auto stageB = [&](int bufi, const __half* Bp) {
        const uint32_t sb = sbase + A_REGION + (uint32_t)(bufi * B_REGION);
#pragma unroll
        for (int it = 0; it < 4; it++) {
            const int row = s_row + it * 16;           // slot row within 64
            const int grow = bperm(row);               // global tile row
            cp16(sb + (uint32_t)(row * RSTRIDE_B + s_c * 16),
                 Bp + grow * R_ + s_c * 8);
        }
    };

    int job = blockIdx.x;

    // ---- prologue for first job: {A,B0} | {B1} | {B2} ----
    {
        int e, bm, bn0; decode_job(job, e, bm, bn0);
        const __half* A  = g_xh + (size_t)e * N_   * R_ + (size_t)bm * R_;
        const __half* Bg = g_wh + (size_t)e * OUT_ * R_ + (size_t)bn0 * R_;
        stageA(A);
        stageB(0, Bg);
        asm volatile("cp.async.commit_group;" ::: "memory");
        stageB(1, Bg + (size_t)BN * R_);
        asm volatile("cp.async.commit_group;" ::: "memory");
        stageB(2, Bg + (size_t)2 * BN * R_);
        asm volatile("cp.async.commit_group;" ::: "memory");
    }

    while (job < NJOBS) {
        int e, bm, bn0; decode_job(job, e, bm, bn0);
        const __half* Bg = g_wh + (size_t)e * OUT_ * R_ + (size_t)bn0 * R_;
        float* C = O + (size_t)e * N_ * OUT_;

        asm volatile("cp.async.wait_group 2;" ::: "memory");
        __syncthreads();

        uint32_t ah[8][8];   // full-K A fragments in regs
#pragma unroll
        for (int ks = 0; ks < 8; ks++)
#pragma unroll
            for (int mt = 0; mt < 2; mt++)
                ldsm4(ah[ks] + mt * 4,
                      sA + a_loff + (uint32_t)(mt * 16 * RSTRIDE_B) + (uint32_t)(ks * 32));

        int nxt = NJOBS;

#pragma unroll 1
        for (int t = 0; t < NTILE; t++) {
            if (t > 0) {
                asm volatile("cp.async.wait_group 2;" ::: "memory");
                __syncthreads();
            }

            if (t < 5) {
                stageB((t + 3) & 3, Bg + (size_t)(t + 3) * BN * R_);
                asm volatile("cp.async.commit_group;" ::: "memory");
            } else if (t == 5) {
                nxt = ctrl[0];
                if (nxt < NJOBS) {
                    int e2, bm2, bn2; decode_job(nxt, e2, bm2, bn2);
                    stageA(g_xh + (size_t)e2 * N_ * R_ + (size_t)bm2 * R_);
                    stageB(0, g_wh + (size_t)e2 * OUT_ * R_ + (size_t)bn2 * R_);
                    asm volatile("cp.async.commit_group;" ::: "memory");
                }
            } else if (t == 6) {
                if (nxt < NJOBS) {
                    int e2, bm2, bn2; decode_job(nxt, e2, bm2, bn2);
                    stageB(1, g_wh + (size_t)e2 * OUT_ * R_ + (size_t)bn2 * R_
                              + (size_t)BN * R_);
                    asm volatile("cp.async.commit_group;" ::: "memory");
                }
            } else {
                if (nxt < NJOBS) {
                    int e2, bm2, bn2; decode_job(nxt, e2, bm2, bn2);
                    stageB(2, g_wh + (size_t)e2 * OUT_ * R_ + (size_t)bn2 * R_
                              + (size_t)2 * BN * R_);
                    asm volatile("cp.async.commit_group;" ::: "memory");
                }
            }
            if (t == 4 && tid == 0) ctrl[0] = atomicAdd(&g_job_ctr, 1);

            const uint32_t bR = sbase + A_REGION + (uint32_t)((t & 3) * B_REGION);

            float acc[2][4][4];
#pragma unroll
            for (int mt = 0; mt < 2; mt++)
#pragma unroll
                for (int nt = 0; nt < 4; nt++)
#pragma unroll
                    for (int q = 0; q < 4; q++)
                        acc[mt][nt][q] = 0.0f;

#pragma unroll
            for (int ks = 0; ks < 8; ks++) {
                const uint32_t kso = (uint32_t)(ks * 32);
                uint32_t bh[8];
                ldsm4(bh + 0, bR + b_loff + 0 * 16 * RSTRIDE_B + kso);
                ldsm4(bh + 4, bR + b_loff + 1 * 16 * RSTRIDE_B + kso);
#pragma unroll
                for (int mt = 0; mt < 2; mt++)
#pragma unroll
                    for (int nt = 0; nt < 4; nt++)
                        mma_f16(acc[mt][nt], ah[ks] + mt * 4, bh + nt * 2);
            }

            // ---- epilogue tile t: permuted layout -> 8x STG.128 per thread ----
            // fragment pair (2p, 2p+1) at quad qc holds output cols p*16+qc*4+{0..3}
            const int colb = bn0 + t * BN;
#pragma unroll
            for (int mt = 0; mt < 2; mt++) {
#pragma unroll
                for (int p = 0; p < 2; p++) {
                    const int row = bm + wm * 32 + mt * 16 + grp;
                    const int col = colb + wn * 32 + p * 16 + qc * 4;
                    float4 v0 = make_float4(acc[mt][2 * p][0], acc[mt][2 * p][1],
                                            acc[mt][2 * p + 1][0], acc[mt][2 * p + 1][1]);
                    float4 v1 = make_float4(acc[mt][2 * p][2], acc[mt][2 * p][3],
                                            acc[mt][2 * p + 1][2], acc[mt][2 * p + 1][3]);
                    __stcs(reinterpret_cast<float4*>(C + (size_t)row * OUT_ + col), v0);
                    __stcs(reinterpret_cast<float4*>(C + (size_t)(row + 8) * OUT_ + col), v1);
                }
            }
        }

        job = nxt;
    }
}

extern "C" void kernel_launch(void* const* d_in, const int* in_sizes, int n_in,
                              void* d_out, int out_size)
{
    const float* x = (const float*)d_in[0];   // [E, N, R]
    const float* w = (const float*)d_in[1];   // [E, OUT, R]
    float* out = (float*)d_out;               // [E, N, OUT]

    const int nvec = (XTOT + WTOT) / 4;
    convert_kernel<<<nvec / 256, 256>>>(x, w);

    cudaFuncSetAttribute(moe_f16_mma_kernel,
                         cudaFuncAttributeMaxDynamicSharedMemorySize, SMEM_BYTES);
    moe_f16_mma_kernel<<<NCTA, THREADS, SMEM_BYTES>>>(out);
}